// round 3
// baseline (speedup 1.0000x reference)
#include <cuda_runtime.h>
#include <cuda_bf16.h>
#include <math.h>

// Problem constants
#define B_   2
#define S_   2048
#define D_   1024
#define H_   16
#define HD_  64
#define BH_  32          // B_*H_
#define M1_  4096        // B_*S_

// ---------------------------------------------------------------------------
// Scratch (static device globals; no runtime allocation allowed)
// ---------------------------------------------------------------------------
__device__ float g_q[M1_ * D_];                       // 16 MB
__device__ float g_k[M1_ * D_];                       // 16 MB
__device__ float g_v[M1_ * D_];                       // 16 MB
__device__ float g_scores[(long)BH_ * S_ * S_];       // 512 MB
__device__ float g_cmax[BH_ * S_];                    // column max
__device__ float g_cden[BH_ * S_];                    // column denom
__device__ float g_attn[M1_ * D_];                    // 16 MB

// ---------------------------------------------------------------------------
// Generic tiled SGEMM:
//   C = epilogue( A[M,K] @ op(B) )   op(B) = B[N,K]^T if TRANSB else B[K,N]
// Batched over blockIdx.z with (batch, head) stride decomposition:
//   z -> b = z/16, h = z%16 ; ptr += b*s?b + h*s?h
// Epilogue options:
//   BIAS:      C += bias[col]
//   MASKSCALE: v = v*scale; if (mask[row*N+col]==0) v = -10000
// Loader option:
//   SOFTA: A element (i, kk) -> exp(a - cmax[z*K + kk]) / cden[z*K + kk]
// ---------------------------------------------------------------------------
template<int BM, int BN, int BK, int TM, int TN,
         bool TRANSB, bool BIAS, bool MASKSCALE, bool SOFTA>
__global__ __launch_bounds__((BM / TM) * (BN / TN))
void gemm_kernel(const float* __restrict__ A, const float* __restrict__ Bm,
                 float* __restrict__ C, const float* __restrict__ bias,
                 const int* __restrict__ mask,
                 const float* __restrict__ cm, const float* __restrict__ cd,
                 int M, int N, int K, int lda, int ldb, int ldc,
                 long sAb, long sAh, long sBb, long sBh, long sCb, long sCh,
                 float scale)
{
    constexpr int NT = (BM / TM) * (BN / TN);

    const int z = blockIdx.z;
    const int bb = z >> 4;
    const int hh = z & 15;
    A  += bb * sAb + hh * sAh;
    Bm += bb * sBb + hh * sBh;
    C  += bb * sCb + hh * sCh;
    if (SOFTA) { cm += (long)z * K; cd += (long)z * K; }

    __shared__ float As[BK][BM];
    __shared__ float Bs[BK][BN];

    const int tid = threadIdx.x;
    const int tx  = tid % (BN / TN);
    const int ty  = tid / (BN / TN);
    const int m0  = blockIdx.y * BM;
    const int n0  = blockIdx.x * BN;

    float acc[TM][TN];
#pragma unroll
    for (int i = 0; i < TM; i++)
#pragma unroll
        for (int j = 0; j < TN; j++) acc[i][j] = 0.f;

    for (int kt = 0; kt < K; kt += BK) {
        // ---- load A tile (BM x BK), stored transposed As[k][m] ----
        constexpr int A4 = BM * BK / 4;
#pragma unroll
        for (int t = tid; t < A4; t += NT) {
            const int r = t / (BK / 4);
            const int c = (t % (BK / 4)) * 4;
            const float4 va = *reinterpret_cast<const float4*>(
                &A[(long)(m0 + r) * lda + kt + c]);
            float x0 = va.x, x1 = va.y, x2 = va.z, x3 = va.w;
            if (SOFTA) {
                x0 = __expf(x0 - cm[kt + c + 0]) / cd[kt + c + 0];
                x1 = __expf(x1 - cm[kt + c + 1]) / cd[kt + c + 1];
                x2 = __expf(x2 - cm[kt + c + 2]) / cd[kt + c + 2];
                x3 = __expf(x3 - cm[kt + c + 3]) / cd[kt + c + 3];
            }
            As[c + 0][r] = x0; As[c + 1][r] = x1;
            As[c + 2][r] = x2; As[c + 3][r] = x3;
        }
        // ---- load B tile ----
        if (TRANSB) {
            constexpr int B4 = BN * BK / 4;
#pragma unroll
            for (int t = tid; t < B4; t += NT) {
                const int r = t / (BK / 4);
                const int c = (t % (BK / 4)) * 4;
                const float4 vb = *reinterpret_cast<const float4*>(
                    &Bm[(long)(n0 + r) * ldb + kt + c]);
                Bs[c + 0][r] = vb.x; Bs[c + 1][r] = vb.y;
                Bs[c + 2][r] = vb.z; Bs[c + 3][r] = vb.w;
            }
        } else {
            constexpr int B4 = BK * BN / 4;
#pragma unroll
            for (int t = tid; t < B4; t += NT) {
                const int r = t / (BN / 4);
                const int c = (t % (BN / 4)) * 4;
                const float4 vb = *reinterpret_cast<const float4*>(
                    &Bm[(long)(kt + r) * ldb + n0 + c]);
                *reinterpret_cast<float4*>(&Bs[r][c]) = vb;
            }
        }
        __syncthreads();

        // ---- compute ----
#pragma unroll
        for (int k = 0; k < BK; k++) {
            float af[TM], bf[TN];
#pragma unroll
            for (int i = 0; i < TM; i++) af[i] = As[k][ty * TM + i];
#pragma unroll
            for (int j = 0; j < TN; j++) bf[j] = Bs[k][tx * TN + j];
#pragma unroll
            for (int i = 0; i < TM; i++)
#pragma unroll
                for (int j = 0; j < TN; j++)
                    acc[i][j] = fmaf(af[i], bf[j], acc[i][j]);
        }
        __syncthreads();
    }

    // ---- epilogue (float4 stores) ----
#pragma unroll
    for (int i = 0; i < TM; i++) {
        const int row = m0 + ty * TM + i;
#pragma unroll
        for (int j0 = 0; j0 < TN; j0 += 4) {
            float tmp[4];
#pragma unroll
            for (int j = 0; j < 4; j++) {
                const int col = n0 + tx * TN + j0 + j;
                float v = acc[i][j0 + j];
                if (MASKSCALE) {
                    v *= scale;
                    if (mask[(long)row * N + col] == 0) v = -10000.0f;
                }
                if (BIAS) v += bias[col];
                tmp[j] = v;
            }
            *reinterpret_cast<float4*>(
                &C[(long)row * ldc + n0 + tx * TN + j0]) =
                make_float4(tmp[0], tmp[1], tmp[2], tmp[3]);
        }
    }
}

// ---------------------------------------------------------------------------
// Column-wise online softmax stats over the query axis i:
//   m[z,j] = max_i s[z,i,j],  d[z,j] = sum_i exp(s[z,i,j] - m[z,j])
// Block of 256 threads handles 256 consecutive columns -> coalesced row reads.
// ---------------------------------------------------------------------------
__global__ __launch_bounds__(256)
void colstats_kernel(const float* __restrict__ Smat,
                     float* __restrict__ m, float* __restrict__ d)
{
    const int z = blockIdx.y;
    const int j = blockIdx.x * blockDim.x + threadIdx.x;
    const float* p = Smat + (long)z * S_ * S_ + j;

    float mx  = -3.0e38f;
    float sum = 0.0f;
#pragma unroll 4
    for (int i = 0; i < S_; i++) {
        const float v = p[(long)i * S_];
        if (v > mx) {
            sum = sum * __expf(mx - v) + 1.0f;
            mx  = v;
        } else {
            sum += __expf(v - mx);
        }
    }
    m[z * S_ + j] = mx;
    d[z * S_ + j] = sum;
}

// ---------------------------------------------------------------------------
// Host launcher
// ---------------------------------------------------------------------------
extern "C" void kernel_launch(void* const* d_in, const int* in_sizes, int n_in,
                              void* d_out, int out_size)
{
    const float* query = (const float*)d_in[0];
    const float* key_  = (const float*)d_in[1];
    const float* value = (const float*)d_in[2];
    const int*   mask  = (const int*)d_in[3];
    const float* Wq = (const float*)d_in[4];
    const float* bq = (const float*)d_in[5];
    const float* Wk = (const float*)d_in[6];
    const float* bk = (const float*)d_in[7];
    const float* Wv = (const float*)d_in[8];
    const float* bv = (const float*)d_in[9];
    const float* Wp = (const float*)d_in[10];
    const float* bp = (const float*)d_in[11];
    float* out = (float*)d_out;

    float *q, *k, *v, *sc, *cm, *cd, *at;
    cudaGetSymbolAddress((void**)&q,  g_q);
    cudaGetSymbolAddress((void**)&k,  g_k);
    cudaGetSymbolAddress((void**)&v,  g_v);
    cudaGetSymbolAddress((void**)&sc, g_scores);
    cudaGetSymbolAddress((void**)&cm, g_cmax);
    cudaGetSymbolAddress((void**)&cd, g_cden);
    cudaGetSymbolAddress((void**)&at, g_attn);

    const long SD  = (long)S_ * D_;          // 2 097 152
    const long SS  = (long)S_ * S_;          // 4 194 304
    const long HSS = (long)H_ * SS;          // 67 108 864

    // ---- 1..3: Q/K/V projections: [4096,1024] = X @ W^T + b ----
    {
        dim3 grid(D_ / 128, M1_ / 128, 1);
        gemm_kernel<128, 128, 16, 8, 8, true, true, false, false>
            <<<grid, 256>>>(query, Wq, q, bq, nullptr, nullptr, nullptr,
                            M1_, D_, D_, D_, D_, D_,
                            0, 0, 0, 0, 0, 0, 1.0f);
        gemm_kernel<128, 128, 16, 8, 8, true, true, false, false>
            <<<grid, 256>>>(key_, Wk, k, bk, nullptr, nullptr, nullptr,
                            M1_, D_, D_, D_, D_, D_,
                            0, 0, 0, 0, 0, 0, 1.0f);
        gemm_kernel<128, 128, 16, 8, 8, true, true, false, false>
            <<<grid, 256>>>(value, Wv, v, bv, nullptr, nullptr, nullptr,
                            M1_, D_, D_, D_, D_, D_,
                            0, 0, 0, 0, 0, 0, 1.0f);
    }

    // ---- 4: scores[z,i,j] = 0.25 * q_h[i,:] . k_h[j,:], masked ----
    {
        dim3 grid(S_ / 128, S_ / 128, BH_);
        gemm_kernel<128, 128, 16, 8, 8, true, false, true, false>
            <<<grid, 256>>>(q, k, sc, nullptr, mask, nullptr, nullptr,
                            S_, S_, HD_, D_, D_, S_,
                            SD, HD_, SD, HD_, HSS, SS, 0.25f);
    }

    // ---- 5: per-column (axis=i) softmax stats ----
    {
        dim3 grid(S_ / 256, BH_);
        colstats_kernel<<<grid, 256>>>(sc, cm, cd);
    }

    // ---- 6: attn @ V with softmax fused into A loader ----
    {
        dim3 grid(HD_ / 64, S_ / 128, BH_);
        gemm_kernel<128, 64, 16, 8, 4, false, false, false, true>
            <<<grid, 256>>>(sc, v, at, nullptr, nullptr, cm, cd,
                            S_, HD_, S_, S_, D_, D_,
                            HSS, SS, SD, HD_, SD, HD_, 1.0f);
    }

    // ---- 7: output projection -> d_out ----
    {
        dim3 grid(D_ / 128, M1_ / 128, 1);
        gemm_kernel<128, 128, 16, 8, 8, true, true, false, false>
            <<<grid, 256>>>(at, Wp, out, bp, nullptr, nullptr, nullptr,
                            M1_, D_, D_, D_, D_, D_,
                            0, 0, 0, 0, 0, 0, 1.0f);
    }
}